// round 15
// baseline (speedup 1.0000x reference)
#include <cuda_runtime.h>
#include <math.h>

#define NNODES 100000
#define HDIM 64

// g_agg is zero at module load; node_kernel re-zeroes it after consuming,
// so it is zero at every kernel_launch entry (correctness run + all replays).
__device__ float4 g_agg[NNODES];
__device__ float4 g_xpad[NNODES];
// table 0: edge MLP (Wp1,bp1,Wp2, no bias2); table 1: vel MLP (W1,b1,W2,b2)
__device__ float g_ts[2][HDIM];
__device__ float g_A[2][HDIM + 1];
__device__ float g_B[2][HDIM + 1];

__device__ __forceinline__ float sqrt_approx(float x) {
    float r;
    asm("sqrt.approx.f32 %0, %1;" : "=f"(r) : "f"(x));
    return r;
}
__device__ __forceinline__ float tanh_approx(float x) {
    float r;
    asm("tanh.approx.f32 %0, %1;" : "=f"(r) : "f"(x));
    return r;
}
__device__ __forceinline__ void red_add_v4(float4* addr, float x, float y,
                                           float z, float w) {
    asm volatile("red.global.add.v4.f32 [%0], {%1, %2, %3, %4};"
                 :: "l"(addr), "f"(x), "f"(y), "f"(z), "f"(w)
                 : "memory");
}

__device__ __forceinline__ int pwl_region(const float* s_t, float v) {
    int lo = 0, hi = HDIM;
#pragma unroll
    for (int s = 0; s < 6; s++) {   // 2^6 = 64
        int mid = (lo + hi) >> 1;
        if (s_t[mid] < v) lo = mid + 1; else hi = mid;
    }
    return lo;
}

// ---------------------------------------------------------------------------
// Prep: smem-staged pack of x -> float4 g_xpad (16B padding => 1-wavefront
// gathers in the edge kernel). Blocks 0/1 also build the two exact PWL
// tables for f(v) = bias2 + sum_h W2[h]*leaky_relu(W1[h]*v + b1[h], 0.2).
// ---------------------------------------------------------------------------
__global__ void __launch_bounds__(256) prep_kernel(
        const float* __restrict__ x, int n,
        const float* __restrict__ Wp1, const float* __restrict__ bp1,
        const float* __restrict__ Wp2,
        const float* __restrict__ W1, const float* __restrict__ b1,
        const float* __restrict__ W2, const float* __restrict__ b2) {
    __shared__ float s_x[768];          // 256 nodes * 3 floats

    int tid = threadIdx.x;
    int base_node = blockIdx.x * 256;
    int total_f4 = (3 * n) / 4;

    if (tid < 192) {
        int f4 = blockIdx.x * 192 + tid;
        if (f4 * 4 + 3 < 3 * n && f4 < total_f4) {
            float4 v = reinterpret_cast<const float4*>(x)[f4];
            s_x[tid * 4 + 0] = v.x;
            s_x[tid * 4 + 1] = v.y;
            s_x[tid * 4 + 2] = v.z;
            s_x[tid * 4 + 3] = v.w;
        } else {
            for (int q = 0; q < 4; q++) {
                int fi = f4 * 4 + q;
                if (fi < 3 * n) s_x[tid * 4 + q] = x[fi];
            }
        }
    }
    __syncthreads();

    int m = base_node + tid;
    if (m < n) {
        g_xpad[m] = make_float4(s_x[3 * tid + 0], s_x[3 * tid + 1],
                                s_x[3 * tid + 2], 0.0f);
    }

    if (blockIdx.x < 2) {
        __shared__ float s_a[HDIM], s_b[HDIM], s_w[HDIM], s_t[HDIM], s_ts[HDIM];
        int which = blockIdx.x;
        const float* W1p = (which == 0) ? Wp1 : W1;
        const float* b1p = (which == 0) ? bp1 : b1;
        const float* W2p = (which == 0) ? Wp2 : W2;
        float bias2 = (which == 1) ? b2[0] : 0.0f;

        int h = tid;
        if (h < HDIM) {
            float aw = W1p[h], bw = b1p[h], ww = W2p[h];
            s_a[h] = aw; s_b[h] = bw; s_w[h] = ww;
            s_t[h] = (aw != 0.0f) ? (-bw / aw) : -1e30f;
        }
        __syncthreads();
        if (h < HDIM) {
            float tv = s_t[h];
            int rank = 0;
            for (int j = 0; j < HDIM; j++) {
                float tj = s_t[j];
                if (tj < tv || (tj == tv && j < h)) rank++;
            }
            s_ts[rank] = tv;
        }
        __syncthreads();
        if (h <= HDIM) {
            float lo = (h == 0)    ? s_ts[0] - 1.0f        : s_ts[h - 1];
            float hi = (h == HDIM) ? s_ts[HDIM - 1] + 1.0f : s_ts[h];
            float rm = 0.5f * (lo + hi);
            float A = 0.0f, B = bias2;
            for (int j = 0; j < HDIM; j++) {
                float z = s_a[j] * rm + s_b[j];
                float s = (z >= 0.0f) ? 1.0f : 0.2f;
                A += s_w[j] * s_a[j] * s;
                B += s_w[j] * s_b[j] * s;
            }
            g_A[which][h] = A;
            g_B[which][h] = B;
            if (h < HDIM) g_ts[which][h] = s_ts[h];
        }
    }
}

// ---------------------------------------------------------------------------
// Edge phase: 2 edges/thread, int2 index loads, block=768: same 48 warps/SM
// occupancy as 512x3 (2 CTAs x 24 warps), but fewer blocks -> less per-block
// fixed cost (table fill + syncthreads + CTA launch/drain). Block-size curve:
// 256 -> 82.0us, 512 -> 80.4us, 1024 -> 82.5us (occupancy cliff).
// At the L1tex random-wavefront floor (2 gathers + 1 red ~= 3 wf per edge).
// ---------------------------------------------------------------------------
__global__ void __launch_bounds__(768) edge_kernel(const int* __restrict__ rowp,
                                                   const int* __restrict__ colp,
                                                   int E) {
    __shared__ float s_t[HDIM];
    __shared__ float s_A[HDIM + 1];
    __shared__ float s_B[HDIM + 1];
    for (int i = threadIdx.x; i < HDIM; i += blockDim.x) s_t[i] = g_ts[0][i];
    for (int i = threadIdx.x; i <= HDIM; i += blockDim.x) {
        s_A[i] = g_A[0][i];
        s_B[i] = g_B[0][i];
    }
    __syncthreads();

    int t = blockIdx.x * blockDim.x + threadIdx.x;
    int e0 = t * 2;
    if (e0 + 1 < E) {
        int2 r2 = __ldcs(reinterpret_cast<const int2*>(rowp + e0));
        int2 c2 = __ldcs(reinterpret_cast<const int2*>(colp + e0));

        float4 xr0 = g_xpad[r2.x];
        float4 xr1 = g_xpad[r2.y];
        float4 xc0 = g_xpad[c2.x];
        float4 xc1 = g_xpad[c2.y];

        float dx0 = xr0.x - xc0.x, dy0 = xr0.y - xc0.y, dz0 = xr0.z - xc0.z;
        float dx1 = xr1.x - xc1.x, dy1 = xr1.y - xc1.y, dz1 = xr1.z - xc1.z;

        float rad0 = sqrt_approx(fmaf(dx0, dx0, fmaf(dy0, dy0, dz0 * dz0)));
        float rad1 = sqrt_approx(fmaf(dx1, dx1, fmaf(dy1, dy1, dz1 * dz1)));

        int k0 = pwl_region(s_t, rad0);
        int k1 = pwl_region(s_t, rad1);

        float eo0 = tanh_approx(fmaf(s_A[k0], rad0, s_B[k0]));
        float eo1 = tanh_approx(fmaf(s_A[k1], rad1, s_B[k1]));

        red_add_v4(&g_agg[r2.x], dx0 * eo0, dy0 * eo0, dz0 * eo0, 1.0f);
        red_add_v4(&g_agg[r2.y], dx1 * eo1, dy1 * eo1, dz1 * eo1, 1.0f);
    } else {
        for (int e = e0; e < E; e++) {
            int r = rowp[e];
            int c = colp[e];
            float4 xr = g_xpad[r];
            float4 xc = g_xpad[c];
            float dx = xr.x - xc.x, dy = xr.y - xc.y, dz = xr.z - xc.z;
            float rad = sqrt_approx(fmaf(dx, dx, fmaf(dy, dy, dz * dz)));
            int k = pwl_region(s_t, rad);
            float eo = tanh_approx(fmaf(s_A[k], rad, s_B[k]));
            red_add_v4(&g_agg[r], dx * eo, dy * eo, dz * eo, 1.0f);
        }
    }
}

// ---------------------------------------------------------------------------
// Node phase: smem-staged, fully coalesced. 256 nodes per 256-thread block.
// g_agg re-zeroed with streaming stores (zero-invariant for replays).
// ---------------------------------------------------------------------------
__global__ void __launch_bounds__(256) node_kernel(
        const float* __restrict__ vel,
        const float* __restrict__ vel_norm,
        float* __restrict__ out, int n) {
    __shared__ float s_t[HDIM];
    __shared__ float s_A[HDIM + 1];
    __shared__ float s_B[HDIM + 1];
    __shared__ float s_v[768];     // staged vel, then reused for staged out

    int tid = threadIdx.x;
    int base = blockIdx.x * 256;
    int i = base + tid;
    bool active = (i < n);
    bool full_block = (base + 256 <= n);

    if (full_block) {
        if (tid < 192) {
            float4 v = reinterpret_cast<const float4*>(vel)[blockIdx.x * 192 + tid];
            s_v[tid * 4 + 0] = v.x;
            s_v[tid * 4 + 1] = v.y;
            s_v[tid * 4 + 2] = v.z;
            s_v[tid * 4 + 3] = v.w;
        }
    } else if (active) {
        s_v[3 * tid + 0] = vel[3 * i + 0];
        s_v[3 * tid + 1] = vel[3 * i + 1];
        s_v[3 * tid + 2] = vel[3 * i + 2];
    }

    float vn = 0.0f;
    float4 xp = make_float4(0, 0, 0, 0);
    float4 ag = make_float4(0, 0, 0, 0);
    if (active) {
        vn = __ldcs(vel_norm + i);
        xp = g_xpad[i];
        ag = g_agg[i];
    }

    for (int j = tid; j < HDIM; j += 256) s_t[j] = g_ts[1][j];
    for (int j = tid; j <= HDIM; j += 256) {
        s_A[j] = g_A[1][j];
        s_B[j] = g_B[1][j];
    }
    __syncthreads();

    float r0 = 0.0f, r1 = 0.0f, r2v = 0.0f;
    if (active) {
        __stcs(&g_agg[i], make_float4(0.0f, 0.0f, 0.0f, 0.0f));

        int k = pwl_region(s_t, vn);
        float scale = fmaf(s_A[k], vn, s_B[k]);
        float invc = 1.0f / fmaxf(ag.w, 1.0f);
        r0 = xp.x + ag.x * invc + s_v[3 * tid + 0] * scale;
        r1 = xp.y + ag.y * invc + s_v[3 * tid + 1] * scale;
        r2v = xp.z + ag.z * invc + s_v[3 * tid + 2] * scale;
    }
    __syncthreads();   // done reading s_v; reuse it for output staging

    if (active) {
        s_v[3 * tid + 0] = r0;
        s_v[3 * tid + 1] = r1;
        s_v[3 * tid + 2] = r2v;
    }
    __syncthreads();

    if (full_block) {
        if (tid < 192) {
            float4 o = make_float4(s_v[tid * 4 + 0], s_v[tid * 4 + 1],
                                   s_v[tid * 4 + 2], s_v[tid * 4 + 3]);
            reinterpret_cast<float4*>(out)[blockIdx.x * 192 + tid] = o;
        }
    } else if (active) {
        out[3 * i + 0] = s_v[3 * tid + 0];
        out[3 * i + 1] = s_v[3 * tid + 1];
        out[3 * i + 2] = s_v[3 * tid + 2];
    }
}

extern "C" void kernel_launch(void* const* d_in, const int* in_sizes, int n_in,
                              void* d_out, int out_size) {
    const float* x        = (const float*)d_in[0];
    const float* vel_norm = (const float*)d_in[1];
    const float* vel      = (const float*)d_in[2];
    const int*   eidx     = (const int*)  d_in[3];
    const float* W1       = (const float*)d_in[4];
    const float* b1       = (const float*)d_in[5];
    const float* W2       = (const float*)d_in[6];
    const float* b2       = (const float*)d_in[7];
    const float* Wp1      = (const float*)d_in[8];
    const float* bp1      = (const float*)d_in[9];
    const float* Wp2      = (const float*)d_in[10];
    float* out = (float*)d_out;

    int n = in_sizes[1];
    int E = in_sizes[3] / 2;
    const int* rowp = eidx;
    const int* colp = eidx + E;

    int nblk_prep = (n + 255) / 256;
    if (nblk_prep < 2) nblk_prep = 2;
    prep_kernel<<<nblk_prep, 256>>>(x, n, Wp1, bp1, Wp2, W1, b1, W2, b2);

    int nthread = (E + 1) / 2;
    edge_kernel<<<(nthread + 767) / 768, 768>>>(rowp, colp, E);
    node_kernel<<<(n + 255) / 256, 256>>>(vel, vel_norm, out, n);
}

// round 16
// speedup vs baseline: 1.0414x; 1.0414x over previous
#include <cuda_runtime.h>
#include <math.h>

#define NNODES 100000
#define HDIM 64

// g_agg is zero at module load; node_kernel re-zeroes it after consuming,
// so it is zero at every kernel_launch entry (correctness run + all replays).
__device__ float4 g_agg[NNODES];
__device__ float4 g_xpad[NNODES];
// table 0: edge MLP (Wp1,bp1,Wp2, no bias2); table 1: vel MLP (W1,b1,W2,b2)
__device__ float g_ts[2][HDIM];
__device__ float g_A[2][HDIM + 1];
__device__ float g_B[2][HDIM + 1];

__device__ __forceinline__ float sqrt_approx(float x) {
    float r;
    asm("sqrt.approx.f32 %0, %1;" : "=f"(r) : "f"(x));
    return r;
}
__device__ __forceinline__ float tanh_approx(float x) {
    float r;
    asm("tanh.approx.f32 %0, %1;" : "=f"(r) : "f"(x));
    return r;
}
__device__ __forceinline__ void red_add_v4(float4* addr, float x, float y,
                                           float z, float w) {
    asm volatile("red.global.add.v4.f32 [%0], {%1, %2, %3, %4};"
                 :: "l"(addr), "f"(x), "f"(y), "f"(z), "f"(w)
                 : "memory");
}

__device__ __forceinline__ int pwl_region(const float* s_t, float v) {
    int lo = 0, hi = HDIM;
#pragma unroll
    for (int s = 0; s < 6; s++) {   // 2^6 = 64
        int mid = (lo + hi) >> 1;
        if (s_t[mid] < v) lo = mid + 1; else hi = mid;
    }
    return lo;
}

// ---------------------------------------------------------------------------
// Prep: smem-staged pack of x -> float4 g_xpad (16B padding => 1-wavefront
// gathers in the edge kernel). Blocks 0/1 also build the two exact PWL
// tables for f(v) = bias2 + sum_h W2[h]*leaky_relu(W1[h]*v + b1[h], 0.2).
// ---------------------------------------------------------------------------
__global__ void __launch_bounds__(256) prep_kernel(
        const float* __restrict__ x, int n,
        const float* __restrict__ Wp1, const float* __restrict__ bp1,
        const float* __restrict__ Wp2,
        const float* __restrict__ W1, const float* __restrict__ b1,
        const float* __restrict__ W2, const float* __restrict__ b2) {
    __shared__ float s_x[768];          // 256 nodes * 3 floats

    int tid = threadIdx.x;
    int base_node = blockIdx.x * 256;
    int total_f4 = (3 * n) / 4;

    if (tid < 192) {
        int f4 = blockIdx.x * 192 + tid;
        if (f4 * 4 + 3 < 3 * n && f4 < total_f4) {
            float4 v = reinterpret_cast<const float4*>(x)[f4];
            s_x[tid * 4 + 0] = v.x;
            s_x[tid * 4 + 1] = v.y;
            s_x[tid * 4 + 2] = v.z;
            s_x[tid * 4 + 3] = v.w;
        } else {
            for (int q = 0; q < 4; q++) {
                int fi = f4 * 4 + q;
                if (fi < 3 * n) s_x[tid * 4 + q] = x[fi];
            }
        }
    }
    __syncthreads();

    int m = base_node + tid;
    if (m < n) {
        g_xpad[m] = make_float4(s_x[3 * tid + 0], s_x[3 * tid + 1],
                                s_x[3 * tid + 2], 0.0f);
    }

    if (blockIdx.x < 2) {
        __shared__ float s_a[HDIM], s_b[HDIM], s_w[HDIM], s_t[HDIM], s_ts[HDIM];
        int which = blockIdx.x;
        const float* W1p = (which == 0) ? Wp1 : W1;
        const float* b1p = (which == 0) ? bp1 : b1;
        const float* W2p = (which == 0) ? Wp2 : W2;
        float bias2 = (which == 1) ? b2[0] : 0.0f;

        int h = tid;
        if (h < HDIM) {
            float aw = W1p[h], bw = b1p[h], ww = W2p[h];
            s_a[h] = aw; s_b[h] = bw; s_w[h] = ww;
            s_t[h] = (aw != 0.0f) ? (-bw / aw) : -1e30f;
        }
        __syncthreads();
        if (h < HDIM) {
            float tv = s_t[h];
            int rank = 0;
            for (int j = 0; j < HDIM; j++) {
                float tj = s_t[j];
                if (tj < tv || (tj == tv && j < h)) rank++;
            }
            s_ts[rank] = tv;
        }
        __syncthreads();
        if (h <= HDIM) {
            float lo = (h == 0)    ? s_ts[0] - 1.0f        : s_ts[h - 1];
            float hi = (h == HDIM) ? s_ts[HDIM - 1] + 1.0f : s_ts[h];
            float rm = 0.5f * (lo + hi);
            float A = 0.0f, B = bias2;
            for (int j = 0; j < HDIM; j++) {
                float z = s_a[j] * rm + s_b[j];
                float s = (z >= 0.0f) ? 1.0f : 0.2f;
                A += s_w[j] * s_a[j] * s;
                B += s_w[j] * s_b[j] * s;
            }
            g_A[which][h] = A;
            g_B[which][h] = B;
            if (h < HDIM) g_ts[which][h] = s_ts[h];
        }
    }
}

// ---------------------------------------------------------------------------
// Edge phase: 2 edges/thread, int2 index loads, block=512 (measured optimum:
// 256 -> 82.0us, 512 -> 80.4us (x2), 768 -> 83.7us, 1024 -> 82.5us).
// At the L1tex random-wavefront floor (2 gathers + 1 red ~= 3 wf per edge).
// ---------------------------------------------------------------------------
__global__ void __launch_bounds__(512) edge_kernel(const int* __restrict__ rowp,
                                                   const int* __restrict__ colp,
                                                   int E) {
    __shared__ float s_t[HDIM];
    __shared__ float s_A[HDIM + 1];
    __shared__ float s_B[HDIM + 1];
    for (int i = threadIdx.x; i < HDIM; i += blockDim.x) s_t[i] = g_ts[0][i];
    for (int i = threadIdx.x; i <= HDIM; i += blockDim.x) {
        s_A[i] = g_A[0][i];
        s_B[i] = g_B[0][i];
    }
    __syncthreads();

    int t = blockIdx.x * blockDim.x + threadIdx.x;
    int e0 = t * 2;
    if (e0 + 1 < E) {
        int2 r2 = __ldcs(reinterpret_cast<const int2*>(rowp + e0));
        int2 c2 = __ldcs(reinterpret_cast<const int2*>(colp + e0));

        float4 xr0 = g_xpad[r2.x];
        float4 xr1 = g_xpad[r2.y];
        float4 xc0 = g_xpad[c2.x];
        float4 xc1 = g_xpad[c2.y];

        float dx0 = xr0.x - xc0.x, dy0 = xr0.y - xc0.y, dz0 = xr0.z - xc0.z;
        float dx1 = xr1.x - xc1.x, dy1 = xr1.y - xc1.y, dz1 = xr1.z - xc1.z;

        float rad0 = sqrt_approx(fmaf(dx0, dx0, fmaf(dy0, dy0, dz0 * dz0)));
        float rad1 = sqrt_approx(fmaf(dx1, dx1, fmaf(dy1, dy1, dz1 * dz1)));

        int k0 = pwl_region(s_t, rad0);
        int k1 = pwl_region(s_t, rad1);

        float eo0 = tanh_approx(fmaf(s_A[k0], rad0, s_B[k0]));
        float eo1 = tanh_approx(fmaf(s_A[k1], rad1, s_B[k1]));

        red_add_v4(&g_agg[r2.x], dx0 * eo0, dy0 * eo0, dz0 * eo0, 1.0f);
        red_add_v4(&g_agg[r2.y], dx1 * eo1, dy1 * eo1, dz1 * eo1, 1.0f);
    } else {
        for (int e = e0; e < E; e++) {
            int r = rowp[e];
            int c = colp[e];
            float4 xr = g_xpad[r];
            float4 xc = g_xpad[c];
            float dx = xr.x - xc.x, dy = xr.y - xc.y, dz = xr.z - xc.z;
            float rad = sqrt_approx(fmaf(dx, dx, fmaf(dy, dy, dz * dz)));
            int k = pwl_region(s_t, rad);
            float eo = tanh_approx(fmaf(s_A[k], rad, s_B[k]));
            red_add_v4(&g_agg[r], dx * eo, dy * eo, dz * eo, 1.0f);
        }
    }
}

// ---------------------------------------------------------------------------
// Node phase: smem-staged, fully coalesced. 256 nodes per 256-thread block.
// g_agg re-zeroed with streaming stores (zero-invariant for replays).
// ---------------------------------------------------------------------------
__global__ void __launch_bounds__(256) node_kernel(
        const float* __restrict__ vel,
        const float* __restrict__ vel_norm,
        float* __restrict__ out, int n) {
    __shared__ float s_t[HDIM];
    __shared__ float s_A[HDIM + 1];
    __shared__ float s_B[HDIM + 1];
    __shared__ float s_v[768];     // staged vel, then reused for staged out

    int tid = threadIdx.x;
    int base = blockIdx.x * 256;
    int i = base + tid;
    bool active = (i < n);
    bool full_block = (base + 256 <= n);

    if (full_block) {
        if (tid < 192) {
            float4 v = reinterpret_cast<const float4*>(vel)[blockIdx.x * 192 + tid];
            s_v[tid * 4 + 0] = v.x;
            s_v[tid * 4 + 1] = v.y;
            s_v[tid * 4 + 2] = v.z;
            s_v[tid * 4 + 3] = v.w;
        }
    } else if (active) {
        s_v[3 * tid + 0] = vel[3 * i + 0];
        s_v[3 * tid + 1] = vel[3 * i + 1];
        s_v[3 * tid + 2] = vel[3 * i + 2];
    }

    float vn = 0.0f;
    float4 xp = make_float4(0, 0, 0, 0);
    float4 ag = make_float4(0, 0, 0, 0);
    if (active) {
        vn = __ldcs(vel_norm + i);
        xp = g_xpad[i];
        ag = g_agg[i];
    }

    for (int j = tid; j < HDIM; j += 256) s_t[j] = g_ts[1][j];
    for (int j = tid; j <= HDIM; j += 256) {
        s_A[j] = g_A[1][j];
        s_B[j] = g_B[1][j];
    }
    __syncthreads();

    float r0 = 0.0f, r1 = 0.0f, r2v = 0.0f;
    if (active) {
        __stcs(&g_agg[i], make_float4(0.0f, 0.0f, 0.0f, 0.0f));

        int k = pwl_region(s_t, vn);
        float scale = fmaf(s_A[k], vn, s_B[k]);
        float invc = 1.0f / fmaxf(ag.w, 1.0f);
        r0 = xp.x + ag.x * invc + s_v[3 * tid + 0] * scale;
        r1 = xp.y + ag.y * invc + s_v[3 * tid + 1] * scale;
        r2v = xp.z + ag.z * invc + s_v[3 * tid + 2] * scale;
    }
    __syncthreads();   // done reading s_v; reuse it for output staging

    if (active) {
        s_v[3 * tid + 0] = r0;
        s_v[3 * tid + 1] = r1;
        s_v[3 * tid + 2] = r2v;
    }
    __syncthreads();

    if (full_block) {
        if (tid < 192) {
            float4 o = make_float4(s_v[tid * 4 + 0], s_v[tid * 4 + 1],
                                   s_v[tid * 4 + 2], s_v[tid * 4 + 3]);
            reinterpret_cast<float4*>(out)[blockIdx.x * 192 + tid] = o;
        }
    } else if (active) {
        out[3 * i + 0] = s_v[3 * tid + 0];
        out[3 * i + 1] = s_v[3 * tid + 1];
        out[3 * i + 2] = s_v[3 * tid + 2];
    }
}

extern "C" void kernel_launch(void* const* d_in, const int* in_sizes, int n_in,
                              void* d_out, int out_size) {
    const float* x        = (const float*)d_in[0];
    const float* vel_norm = (const float*)d_in[1];
    const float* vel      = (const float*)d_in[2];
    const int*   eidx     = (const int*)  d_in[3];
    const float* W1       = (const float*)d_in[4];
    const float* b1       = (const float*)d_in[5];
    const float* W2       = (const float*)d_in[6];
    const float* b2       = (const float*)d_in[7];
    const float* Wp1      = (const float*)d_in[8];
    const float* bp1      = (const float*)d_in[9];
    const float* Wp2      = (const float*)d_in[10];
    float* out = (float*)d_out;

    int n = in_sizes[1];
    int E = in_sizes[3] / 2;
    const int* rowp = eidx;
    const int* colp = eidx + E;

    int nblk_prep = (n + 255) / 256;
    if (nblk_prep < 2) nblk_prep = 2;
    prep_kernel<<<nblk_prep, 256>>>(x, n, Wp1, bp1, Wp2, W1, b1, W2, b2);

    int nthread = (E + 1) / 2;
    edge_kernel<<<(nthread + 511) / 512, 512>>>(rowp, colp, E);
    node_kernel<<<(n + 255) / 256, 256>>>(vel, vel_norm, out, n);
}